// round 2
// baseline (speedup 1.0000x reference)
#include <cuda_runtime.h>
#include <cstdint>

// Problem constants
#define BB 16
#define TT 1024
#define HH 256
#define LL 2048
#define TL 32                 // queries (l) per block
#define NBLK (BB * (LL / TL)) // 1024 blocks

// Shared-memory pitches (floats). All row strides are multiples of 4 floats
// (16B) so float4 smem accesses stay aligned.
#define QP  260   // Qs:  [TL][QP]
#define XTP 132   // Xu (GEMM1 staging, transposed): [16][XTP]
#define X2P 260   // Xu (GEMM2 staging):             [16][X2P]

#define SM_FLOATS (TL * QP + TL * TT + 16 * X2P)   // 8320 + 32768 + 4160 = 45248 (180,992 B)

__global__ void __launch_bounds__(256, 1)
pla_kernel(const float* __restrict__ X,          // (B,T,H)
           const void*  __restrict__ labels_raw, // (B,L) int32 or int64 (detected)
           const float* __restrict__ table,      // (C+1,H)
           float* __restrict__ logits,           // (B,L,H)
           float* __restrict__ att)              // (B,L,T)
{
    extern __shared__ float sm[];
    float* Qs = sm;                 // [TL][QP]
    float* Ss = sm + TL * QP;       // [TL][TT]
    float* Xu = Ss + TL * TT;       // staging union (GEMM1 transposed / GEMM2)

    const int tid = threadIdx.x;
    const int b   = blockIdx.x >> 6;       // / (LL/TL)=64
    const int lt  = blockIdx.x & 63;
    const int l0  = lt * TL;
    const float* Xb = X + (size_t)b * TT * HH;

    // ---- labels dtype detection (int64 vs int32) ----
    // int64 little-endian with values < 2^31 => odd int32 words are all zero.
    __shared__ int s_is64;
    if (tid == 0) {
        const int* li = (const int*)labels_raw;
        int z = li[1] | li[3] | li[5] | li[7] | li[9] | li[11] | li[13] | li[15];
        s_is64 = (z == 0) ? 1 : 0;
    }
    __syncthreads();
    const bool is64 = (s_is64 != 0);

    // ---- gather Q rows (table[labels]) into smem ----
    {
        const int q  = tid >> 3;            // 0..31
        const int c0 = (tid & 7) * 4;       // 0..28
        const long long lidx = (long long)b * LL + l0 + q;
        const long long lab = is64 ? ((const long long*)labels_raw)[lidx]
                                   : (long long)((const int*)labels_raw)[lidx];
        const float* row = table + (size_t)lab * HH;
        #pragma unroll
        for (int j = 0; j < 8; j++) {
            *(float4*)(Qs + q * QP + c0 + j * 32) =
                *(const float4*)(row + c0 + j * 32);
        }
    }
    __syncthreads();

    const int qg = tid >> 5;    // 0..7  (q group)
    const int tg = tid & 31;    // 0..31 (t / h group)
    const int q0 = qg * 4;

    // =======================================================================
    // GEMM1: S[q][t] = sum_k Q[q][k] * X[t][k]
    // t-chunks of 128, k-chunks of 16 (staged transposed in smem, pipelined)
    // =======================================================================
    const int t0a = tid >> 2;   // 0..63 (staging row)
    const int k4a = tid & 3;    // 0..3  (staging k-quad)
    for (int tc = 0; tc < TT; tc += 128) {
        float acc[4][4];
        #pragma unroll
        for (int i = 0; i < 4; i++) {
            acc[i][0] = 0.f; acc[i][1] = 0.f; acc[i][2] = 0.f; acc[i][3] = 0.f;
        }

        // prefetch first k-chunk
        float4 p0 = *(const float4*)(Xb + (size_t)(tc + t0a)      * HH + k4a * 4);
        float4 p1 = *(const float4*)(Xb + (size_t)(tc + t0a + 64) * HH + k4a * 4);

        for (int kc = 0; kc < HH; kc += 16) {
            // store staged chunk (transposed: Xu[k][t])
            Xu[(k4a * 4 + 0) * XTP + t0a]      = p0.x;
            Xu[(k4a * 4 + 1) * XTP + t0a]      = p0.y;
            Xu[(k4a * 4 + 2) * XTP + t0a]      = p0.z;
            Xu[(k4a * 4 + 3) * XTP + t0a]      = p0.w;
            Xu[(k4a * 4 + 0) * XTP + t0a + 64] = p1.x;
            Xu[(k4a * 4 + 1) * XTP + t0a + 64] = p1.y;
            Xu[(k4a * 4 + 2) * XTP + t0a + 64] = p1.z;
            Xu[(k4a * 4 + 3) * XTP + t0a + 64] = p1.w;
            __syncthreads();
            if (kc + 16 < HH) {  // prefetch next chunk (overlaps compute)
                p0 = *(const float4*)(Xb + (size_t)(tc + t0a)      * HH + kc + 16 + k4a * 4);
                p1 = *(const float4*)(Xb + (size_t)(tc + t0a + 64) * HH + kc + 16 + k4a * 4);
            }
            #pragma unroll
            for (int k4 = 0; k4 < 4; k4++) {
                float qv[4][4];
                #pragma unroll
                for (int i = 0; i < 4; i++) {
                    float4 v = *(const float4*)(Qs + (q0 + i) * QP + kc + k4 * 4);
                    qv[i][0] = v.x; qv[i][1] = v.y; qv[i][2] = v.z; qv[i][3] = v.w;
                }
                #pragma unroll
                for (int kk = 0; kk < 4; kk++) {
                    float4 xv = *(const float4*)(Xu + (k4 * 4 + kk) * XTP + tg * 4);
                    float xf[4] = {xv.x, xv.y, xv.z, xv.w};
                    #pragma unroll
                    for (int i = 0; i < 4; i++) {
                        const float qq = qv[i][kk];
                        acc[i][0] = fmaf(qq, xf[0], acc[i][0]);
                        acc[i][1] = fmaf(qq, xf[1], acc[i][1]);
                        acc[i][2] = fmaf(qq, xf[2], acc[i][2]);
                        acc[i][3] = fmaf(qq, xf[3], acc[i][3]);
                    }
                }
            }
            __syncthreads();
        }
        #pragma unroll
        for (int i = 0; i < 4; i++) {
            *(float4*)(Ss + (q0 + i) * TT + tc + tg * 4) =
                make_float4(acc[i][0], acc[i][1], acc[i][2], acc[i][3]);
        }
    }
    __syncthreads();

    // =======================================================================
    // Softmax over T (in smem), write attention to gmem, keep P in smem
    // =======================================================================
    {
        const int w    = tid >> 5;
        const int lane = tid & 31;
        #pragma unroll
        for (int r = 0; r < 4; r++) {
            const int q = w * 4 + r;
            float* row = Ss + q * TT;
            float m = -3.4e38f;
            #pragma unroll
            for (int i = 0; i < 32; i++) m = fmaxf(m, row[lane + i * 32]);
            #pragma unroll
            for (int o = 16; o > 0; o >>= 1)
                m = fmaxf(m, __shfl_xor_sync(0xffffffffu, m, o));
            float ssum = 0.f;
            #pragma unroll
            for (int i = 0; i < 32; i++) {
                float e = __expf(row[lane + i * 32] - m);
                row[lane + i * 32] = e;
                ssum += e;
            }
            #pragma unroll
            for (int o = 16; o > 0; o >>= 1)
                ssum += __shfl_xor_sync(0xffffffffu, ssum, o);
            const float inv = 1.0f / ssum;
            float* gout = att + ((size_t)b * LL + l0 + q) * TT;
            #pragma unroll
            for (int i = 0; i < 8; i++) {
                const int t = lane * 4 + i * 128;
                float4 v = *(float4*)(row + t);
                v.x *= inv; v.y *= inv; v.z *= inv; v.w *= inv;
                *(float4*)(row + t)  = v;
                *(float4*)(gout + t) = v;
            }
        }
    }
    __syncthreads();

    // =======================================================================
    // GEMM2: O[q][h] = sum_t P[q][t] * X[t][h]
    // t-chunks of 16 (staged in smem, pipelined), micro-tile 4q x 8h/thread
    // =======================================================================
    {
        const int hg = tg;              // 0..31; thread owns h = hg*4..+3 and 128+hg*4..+3
        float o[4][8];
        #pragma unroll
        for (int i = 0; i < 4; i++)
            #pragma unroll
            for (int j = 0; j < 8; j++) o[i][j] = 0.f;

        const int r2 = tid >> 4;         // 0..15 (staging row)
        const int c2 = (tid & 15) * 4;   // 0..60
        float4 pr[4];
        #pragma unroll
        for (int j = 0; j < 4; j++)
            pr[j] = *(const float4*)(Xb + (size_t)r2 * HH + c2 + j * 64);

        for (int tc = 0; tc < TT; tc += 16) {
            #pragma unroll
            for (int j = 0; j < 4; j++)
                *(float4*)(Xu + r2 * X2P + c2 + j * 64) = pr[j];
            __syncthreads();
            if (tc + 16 < TT) {
                #pragma unroll
                for (int j = 0; j < 4; j++)
                    pr[j] = *(const float4*)(Xb + (size_t)(tc + 16 + r2) * HH + c2 + j * 64);
            }
            #pragma unroll
            for (int t4 = 0; t4 < 4; t4++) {
                float pv[4][4];
                #pragma unroll
                for (int i = 0; i < 4; i++) {
                    float4 v = *(const float4*)(Ss + (q0 + i) * TT + tc + t4 * 4);
                    pv[i][0] = v.x; pv[i][1] = v.y; pv[i][2] = v.z; pv[i][3] = v.w;
                }
                #pragma unroll
                for (int tt = 0; tt < 4; tt++) {
                    float4 xa  = *(const float4*)(Xu + (t4 * 4 + tt) * X2P + hg * 4);
                    float4 xb2 = *(const float4*)(Xu + (t4 * 4 + tt) * X2P + 128 + hg * 4);
                    float xf[8] = {xa.x, xa.y, xa.z, xa.w, xb2.x, xb2.y, xb2.z, xb2.w};
                    #pragma unroll
                    for (int i = 0; i < 4; i++) {
                        const float pp = pv[i][tt];
                        #pragma unroll
                        for (int j = 0; j < 8; j++)
                            o[i][j] = fmaf(pp, xf[j], o[i][j]);
                    }
                }
            }
            __syncthreads();
        }
        #pragma unroll
        for (int i = 0; i < 4; i++) {
            float* dst = logits + ((size_t)b * LL + l0 + q0 + i) * HH;
            *(float4*)(dst + hg * 4)       = make_float4(o[i][0], o[i][1], o[i][2], o[i][3]);
            *(float4*)(dst + 128 + hg * 4) = make_float4(o[i][4], o[i][5], o[i][6], o[i][7]);
        }
    }
}

extern "C" void kernel_launch(void* const* d_in, const int* in_sizes, int n_in,
                              void* d_out, int out_size)
{
    const float* X      = (const float*)d_in[0];
    const void*  labels = d_in[1];
    const float* table  = (const float*)d_in[2];
    float* logits = (float*)d_out;
    float* att    = logits + (size_t)BB * LL * HH;

    const size_t smem = (size_t)SM_FLOATS * sizeof(float);  // 180,992 B
    cudaFuncSetAttribute(pla_kernel, cudaFuncAttributeMaxDynamicSharedMemorySize, (int)smem);
    pla_kernel<<<NBLK, 256, smem>>>(X, labels, table, logits, att);
}

// round 4
// speedup vs baseline: 5.1549x; 5.1549x over previous
#include <cuda_runtime.h>
#include <cuda_fp16.h>
#include <cstdint>

#define BB 16
#define TT 1024
#define HH 256
#define LL 2048
#define MQ 64          // queries per CTA
#define TCHK 64
#define NCHUNK (TT / TCHK)

// smem pitches (in halves)
#define QP 264
#define XP 264
#define EP 1048

// smem byte offsets
#define SO_RS4  0                      // float rs4[4][64]
#define SO_INV  1024                   // float inv[64]
#define SO_FLAG 1536
#define SO_Q    2048                   // 64*264*2 = 33792
#define SO_X    (2048 + 33792)         // 64*264*2 = 33792
#define SO_E    (2048 + 33792 + 33792) // 64*1048*2 = 134144
#define SMEM_BYTES (SO_E + 64 * EP * 2)   // 203776

__device__ __forceinline__ uint32_t smem_u32(const void* p) {
    uint32_t a;
    asm("{ .reg .u64 t; cvta.to.shared.u64 t, %1; cvt.u32.u64 %0, t; }" : "=r"(a) : "l"(p));
    return a;
}
__device__ __forceinline__ void ldsm4(uint32_t a, uint32_t* r) {
    asm volatile("ldmatrix.sync.aligned.m8n8.x4.shared.b16 {%0,%1,%2,%3}, [%4];"
                 : "=r"(r[0]), "=r"(r[1]), "=r"(r[2]), "=r"(r[3]) : "r"(a));
}
__device__ __forceinline__ void ldsm4t(uint32_t a, uint32_t* r) {
    asm volatile("ldmatrix.sync.aligned.m8n8.x4.trans.shared.b16 {%0,%1,%2,%3}, [%4];"
                 : "=r"(r[0]), "=r"(r[1]), "=r"(r[2]), "=r"(r[3]) : "r"(a));
}
__device__ __forceinline__ void mma16816(float* d, const uint32_t* a, const uint32_t* b) {
    asm volatile("mma.sync.aligned.m16n8k16.row.col.f32.f16.f16.f32 "
                 "{%0,%1,%2,%3}, {%4,%5,%6,%7}, {%8,%9}, {%0,%1,%2,%3};"
                 : "+f"(d[0]), "+f"(d[1]), "+f"(d[2]), "+f"(d[3])
                 : "r"(a[0]), "r"(a[1]), "r"(a[2]), "r"(a[3]), "r"(b[0]), "r"(b[1]));
}

__global__ void __launch_bounds__(256, 1)
pla_mma(const float* __restrict__ X,          // (B,T,H)
        const void*  __restrict__ labels_raw, // (B,L) int32/int64
        const float* __restrict__ table,      // (C+1,H)
        float* __restrict__ logits,           // (B,L,H)
        float* __restrict__ att)              // (B,L,T)
{
    extern __shared__ char sm[];
    float*  rs4  = (float*)(sm + SO_RS4);
    float*  inv  = (float*)(sm + SO_INV);
    __half* Qs   = (__half*)(sm + SO_Q);
    __half* Xs   = (__half*)(sm + SO_X);
    __half* Es   = (__half*)(sm + SO_E);
    const uint32_t smb = smem_u32(sm);
    const uint32_t Qb = smb + SO_Q, Xb_s = smb + SO_X, Eb = smb + SO_E;

    const int tid = threadIdx.x, lane = tid & 31, w = tid >> 5;
    const int wm = w & 1, wn = w >> 1;              // warp grid: 2(M) x 4(N)
    const int m0 = wm * 32;
    const int b = blockIdx.x >> 5, lt = blockIdx.x & 31, l0 = lt * MQ;
    const size_t bL = (size_t)b * LL;
    const float* Xg = X + (size_t)b * TT * HH;

    rs4[tid] = 0.f;   // 4*64 floats

    // labels dtype detection (int64 LE, values < 2^31 => odd words zero)
    int* flag = (int*)(sm + SO_FLAG);
    if (tid == 0) {
        const int* li = (const int*)labels_raw;
        *flag = ((li[1] | li[3] | li[5] | li[7] | li[9] | li[11] | li[13] | li[15]) == 0);
    }
    __syncthreads();
    const bool is64 = (*flag != 0);

    // ---- gather Q (table[labels]) -> fp16 smem ----
    {
        const int q = tid >> 2, c0 = (tid & 3) * 4;
        const long long lidx = (long long)b * LL + l0 + q;
        const long long lab = is64 ? ((const long long*)labels_raw)[lidx]
                                   : (long long)((const int*)labels_raw)[lidx];
        const float* row = table + (size_t)lab * HH;
        #pragma unroll
        for (int j = 0; j < 16; j++) {
            const int col = c0 + j * 16;
            float4 v = *(const float4*)(row + col);
            *(half2*)(Qs + q * QP + col)     = __floats2half2_rn(v.x, v.y);
            *(half2*)(Qs + q * QP + col + 2) = __floats2half2_rn(v.z, v.w);
        }
    }

    // ---- prefetch X chunk 0 ----
    float4 pr[16];
    {
        const int c4 = (tid & 63) * 4, tr0 = tid >> 6;
        #pragma unroll
        for (int i = 0; i < 16; i++)
            pr[i] = *(const float4*)(Xg + (size_t)(tr0 + i * 4) * HH + c4);
    }

    // per-thread running row sums (4 rows: mf{0,1} x {r, r+8})
    float rsum[4] = {0.f, 0.f, 0.f, 0.f};
    float o[64];
    #pragma unroll
    for (int i = 0; i < 64; i++) o[i] = 0.f;

    // ldmatrix base addresses
    const uint32_t a1_0 = Qb + (uint32_t)(((m0 + (lane & 15)) * QP + ((lane >> 4) << 3)) * 2);
    const uint32_t b1_0 = Xb_s + (uint32_t)(((wn * 16 + (lane & 7) + ((lane >> 4) << 3)) * XP
                                             + ((lane >> 3) & 1) * 8) * 2);
    const uint32_t a2_0 = Eb + (uint32_t)(((m0 + (lane & 15)) * EP + ((lane >> 4) << 3)) * 2);
    const uint32_t b2_0 = Xb_s + (uint32_t)(((lane & 15) * XP + wn * 64 + ((lane >> 4) << 3)) * 2);

    const int r = lane >> 2, c2 = (lane & 3) * 2;

    for (int tc = 0; tc < NCHUNK; tc++) {
        // ---- store prefetched chunk -> Xs fp16 ----
        {
            const int c4 = (tid & 63) * 4, tr0 = tid >> 6;
            #pragma unroll
            for (int i = 0; i < 16; i++) {
                const int t = tr0 + i * 4;
                *(half2*)(Xs + t * XP + c4)     = __floats2half2_rn(pr[i].x, pr[i].y);
                *(half2*)(Xs + t * XP + c4 + 2) = __floats2half2_rn(pr[i].z, pr[i].w);
            }
        }
        __syncthreads();

        // ---- MMA1: S[64 x 64] = Q * Xchunk^T  (K = 256) ----
        float sa[4][4];
        #pragma unroll
        for (int i = 0; i < 4; i++)
            for (int j = 0; j < 4; j++) sa[i][j] = 0.f;
        #pragma unroll 4
        for (int k = 0; k < 16; k++) {
            uint32_t A0[4], A1[4], Bv[4];
            ldsm4(a1_0 + k * 32, A0);
            ldsm4(a1_0 + 16 * QP * 2 + k * 32, A1);
            ldsm4(b1_0 + k * 32, Bv);
            mma16816(sa[0], A0, Bv);
            mma16816(sa[1], A0, Bv + 2);
            mma16816(sa[2], A1, Bv);
            mma16816(sa[3], A1, Bv + 2);
        }

        // ---- prefetch next chunk (overlaps epilogue + MMA2) ----
        if (tc + 1 < NCHUNK) {
            const int c4 = (tid & 63) * 4, tr0 = tid >> 6;
            const float* src = Xg + (size_t)(tc + 1) * TCHK * HH;
            #pragma unroll
            for (int i = 0; i < 16; i++)
                pr[i] = *(const float4*)(src + (size_t)(tr0 + i * 4) * HH + c4);
        }

        // ---- epilogue: e = exp(s) -> Es fp16, running row sums ----
        #pragma unroll
        for (int mf = 0; mf < 2; mf++) {
            #pragma unroll
            for (int nf = 0; nf < 2; nf++) {
                float* s = sa[mf * 2 + nf];
                const float e0 = __expf(s[0]), e1 = __expf(s[1]);
                const float e2 = __expf(s[2]), e3 = __expf(s[3]);
                rsum[mf * 2 + 0] += e0 + e1;
                rsum[mf * 2 + 1] += e2 + e3;
                const int row0 = m0 + mf * 16 + r;
                const int col = tc * TCHK + wn * 16 + nf * 8 + c2;
                *(half2*)(Es + row0 * EP + col)       = __floats2half2_rn(e0, e1);
                *(half2*)(Es + (row0 + 8) * EP + col) = __floats2half2_rn(e2, e3);
            }
        }
        __syncthreads();   // Es chunk visible to all warps

        // ---- MMA2: O[64 x 256] += E_chunk[64 x 64] * Xchunk[64 x 256] ----
        #pragma unroll
        for (int kst = 0; kst < 4; kst++) {
            uint32_t A0[4], A1[4], Bv[4][4];
            ldsm4(a2_0 + tc * 128 + kst * 32, A0);
            ldsm4(a2_0 + 16 * EP * 2 + tc * 128 + kst * 32, A1);
            #pragma unroll
            for (int nb = 0; nb < 4; nb++)
                ldsm4t(b2_0 + kst * 16 * XP * 2 + nb * 32, Bv[nb]);
            #pragma unroll
            for (int nf = 0; nf < 8; nf++) {
                const uint32_t* bp = &Bv[nf >> 1][(nf & 1) * 2];
                mma16816(&o[nf * 4],        A0, bp);
                mma16816(&o[32 + nf * 4],   A1, bp);
            }
        }
        __syncthreads();   // Xs free for next chunk
    }

    // ---- reduce row sums across quad lanes, publish, compute inverses ----
    #pragma unroll
    for (int mf = 0; mf < 2; mf++) {
        #pragma unroll
        for (int h = 0; h < 2; h++) {
            float v = rsum[mf * 2 + h];
            v += __shfl_xor_sync(0xffffffffu, v, 1);
            v += __shfl_xor_sync(0xffffffffu, v, 2);
            if ((lane & 3) == 0)
                rs4[wn * 64 + m0 + mf * 16 + h * 8 + r] = v;
        }
    }
    __syncthreads();
    if (tid < 64)
        inv[tid] = 1.0f / (rs4[tid] + rs4[64 + tid] + rs4[128 + tid] + rs4[192 + tid]);
    __syncthreads();

    // ---- write logits (scaled O fragments) ----
    #pragma unroll
    for (int mf = 0; mf < 2; mf++) {
        #pragma unroll
        for (int nf = 0; nf < 8; nf++) {
            const float* ov = &o[mf * 32 + nf * 4];
            const int r0 = m0 + mf * 16 + r;
            const int col = wn * 64 + nf * 8 + c2;
            const float i0 = inv[r0], i1 = inv[r0 + 8];
            float* d0 = logits + (bL + l0 + r0) * HH + col;
            float* d1 = logits + (bL + l0 + r0 + 8) * HH + col;
            *(float2*)d0 = make_float2(ov[0] * i0, ov[1] * i0);
            *(float2*)d1 = make_float2(ov[2] * i1, ov[3] * i1);
        }
    }

    // ---- write normalized attention from Es (coalesced) ----
    #pragma unroll
    for (int sub = 0; sub < 2; sub++) {
        const int rr = w * 8 + sub * 4 + (lane >> 3);
        const int cb = (lane & 7) * 4;
        const float iv = inv[rr];
        float* gd = att + (bL + l0 + rr) * TT;
        const __half* es = Es + rr * EP;
        #pragma unroll
        for (int j = 0; j < 32; j++) {
            const int col = cb + j * 32;
            float2 f0 = __half22float2(*(const half2*)(es + col));
            float2 f1 = __half22float2(*(const half2*)(es + col + 2));
            *(float4*)(gd + col) = make_float4(f0.x * iv, f0.y * iv, f1.x * iv, f1.y * iv);
        }
    }
}

extern "C" void kernel_launch(void* const* d_in, const int* in_sizes, int n_in,
                              void* d_out, int out_size)
{
    const float* X      = (const float*)d_in[0];
    const void*  labels = d_in[1];
    const float* table  = (const float*)d_in[2];
    float* logits = (float*)d_out;
    float* att    = logits + (size_t)BB * LL * HH;

    cudaFuncSetAttribute(pla_mma, cudaFuncAttributeMaxDynamicSharedMemorySize, SMEM_BYTES);
    pla_mma<<<BB * (LL / MQ), 256, SMEM_BYTES>>>(X, labels, table, logits, att);
}